// round 14
// baseline (speedup 1.0000x reference)
#include <cuda_runtime.h>
#include <math.h>

#define T_LEN   1024
#define NBATCH  256
#define NCHUNK  64
#define CHUNKL  16
#define RIC_CAP 256

// ---------------- device scratch (no allocations allowed) ----------------
__device__ __align__(16) float g_M[T_LEN * 128];       // M_t, [t][16][8]
__device__ __align__(16) float g_Minv[T_LEN * 64];     // inv(innov_var_t), [t][8][8]
__device__ __align__(16) float g_logdet[T_LEN];        // logdet(innov_var_t)
__device__ __align__(16) float g_G[T_LEN * 256];       // G_t = A - M_t*B
__device__ __align__(16) float g_atld[T_LEN * 16];     // atld_t = a - M_t*b
__device__ __align__(16) float g_C[T_LEN * 128];       // C_t = B*Phi_t, [t][8][16]
__device__ __align__(16) float g_Q[NCHUNK * 256];      // Q_c = sum C^T N C
__device__ __align__(16) float g_ldc[NCHUNK];          // per-chunk logdet sum
__device__ __align__(16) float g_H[NCHUNK * 256];      // chunk transition 16x16
__device__ __align__(16) float g_p[NCHUNK * NBATCH * 16];        // zero-init response
__device__ __align__(16) float g_l[NCHUNK * NBATCH * 16];        // lvec per batch-chunk
__device__ __align__(16) float g_cnst[NCHUNK * NBATCH];          // d^T N d sums
__device__ __align__(16) float g_mustart[NCHUNK * NBATCH * 16];  // chunk entry states
__device__ int g_conv;

// =====================================================================
// Phase 1: batch-independent Riccati. ΔM freeze threshold 4e-3.
// =====================================================================
__global__ void __launch_bounds__(256, 1)
riccati_kernel(const float* __restrict__ A, const float* __restrict__ B,
               const float* __restrict__ U, const float* __restrict__ V,
               const float* __restrict__ W, const float* __restrict__ A0)
{
    __shared__ float sS[16][16];
    __shared__ float sAS[16][16];
    __shared__ float sSBt[16][8];
    __shared__ float sR[8][8];
    __shared__ float sInv[8][8];
    __shared__ float sP[16][8];
    __shared__ float sASA[16][16];
    __shared__ float sM[16][8];
    __shared__ float sMprev[16][8];
    __shared__ float sA[16][16], sB[8][16], sQ[16][16], sV[8][8];
    __shared__ int s_max;
    __shared__ int s_done;

    const unsigned FULL = 0xffffffffu;
    const int tid = threadIdx.x;
    const int i16 = tid >> 4, j16 = tid & 15;

    sA[i16][j16] = A[tid];
    sS[i16][j16] = A0[tid];
    if (tid < 128) { sB[tid >> 4][tid & 15] = B[tid]; sMprev[tid >> 3][tid & 7] = 0.f; }
    if (tid < 64)  sV[tid >> 3][tid & 7]  = V[tid];
    if (tid == 0) { s_done = 0; s_max = 0; }
    __syncthreads();

    {
        float acc = 0.f;
        #pragma unroll
        for (int k = 0; k < 16; ++k) acc += W[i16 * 16 + k] * U[k * 16 + j16];
        sAS[i16][j16] = acc;
    }
    __syncthreads();
    {
        float acc = 0.f;
        #pragma unroll
        for (int k = 0; k < 16; ++k) acc += sAS[i16][k] * W[j16 * 16 + k];
        sQ[i16][j16] = acc;
    }
    __syncthreads();

    int conv_t = RIC_CAP - 1;

    for (int t = 0; t < RIC_CAP; ++t) {
        {
            float acc = 0.f;
            #pragma unroll
            for (int k = 0; k < 16; ++k) acc += sA[i16][k] * sS[k][j16];
            sAS[i16][j16] = acc;
        }
        if (tid < 128) {
            int i = tid >> 3, j = tid & 7;
            float acc = 0.f;
            #pragma unroll
            for (int k = 0; k < 16; ++k) acc += sS[i][k] * sB[j][k];
            sSBt[i][j] = acc;
        }
        __syncthreads();

        if (tid < 64) {
            int i = tid >> 3, j = tid & 7;
            float acc = sV[i][j];
            #pragma unroll
            for (int k = 0; k < 16; ++k) acc += sB[i][k] * sSBt[k][j];
            sR[i][j] = acc;
        } else if (tid < 192) {
            int id = tid - 64;
            int i = id >> 3, j = id & 7;
            float acc = 0.f;
            #pragma unroll
            for (int k = 0; k < 16; ++k) acc += sA[i][k] * sSBt[k][j];
            sP[i][j] = acc;
        } else {
            int id = tid - 192;
            int i = id >> 4, j = id & 15;
            float acc = sQ[i][j];
            #pragma unroll
            for (int k = 0; k < 16; ++k) acc += sAS[i][k] * sA[j][k];
            sASA[i][j] = acc;
            if (tid == 255) s_max = 0;
        }
        __syncthreads();

        if (tid < 32) {
            int lane = tid;
            int j = lane >> 2, cq = lane & 3;
            float v[4];
            if (cq < 2) {
                #pragma unroll
                for (int r = 0; r < 4; ++r) v[r] = sR[j][cq * 4 + r];
            } else {
                #pragma unroll
                for (int r = 0; r < 4; ++r)
                    v[r] = ((cq - 2) * 4 + r == j) ? 1.f : 0.f;
            }
            float prod = 1.f, mydiag = 1.f;
            #pragma unroll
            for (int k = 0; k < 8; ++k) {
                float pk = __shfl_sync(FULL, v[k & 3], (k << 2) | (k >> 2));
                float fk = __shfl_sync(FULL, v[k & 3], (lane & 28) | (k >> 2));
                float r0 = __shfl_sync(FULL, v[0], (k << 2) | cq);
                float r1 = __shfl_sync(FULL, v[1], (k << 2) | cq);
                float r2 = __shfl_sync(FULL, v[2], (k << 2) | cq);
                float r3 = __shfl_sync(FULL, v[3], (k << 2) | cq);
                if (j != k) {
                    float c = fk * __frcp_rn(pk);
                    v[0] = fmaf(-c, r0, v[0]);
                    v[1] = fmaf(-c, r1, v[1]);
                    v[2] = fmaf(-c, r2, v[2]);
                    v[3] = fmaf(-c, r3, v[3]);
                } else {
                    mydiag = pk;
                }
                prod *= pk;
            }
            float rd = __frcp_rn(mydiag);
            if (cq >= 2) {
                #pragma unroll
                for (int r = 0; r < 4; ++r) {
                    int c = (cq - 2) * 4 + r;
                    float iv = v[r] * rd;
                    sInv[j][c] = iv;
                    g_Minv[t * 64 + j * 8 + c] = iv;
                }
            }
            if (lane == 0) g_logdet[t] = __logf(prod);
        } else if (tid < 224) {
            int id = tid + 32;
            int i = id >> 4, j = id & 15;
            float acc = sQ[i][j];
            #pragma unroll
            for (int k = 0; k < 16; ++k) acc += sAS[i][k] * sA[j][k];
            sASA[i][j] = acc;
        }
        __syncthreads();

        if (tid < 128) {
            int i = tid >> 3, j = tid & 7;
            float acc = 0.f;
            #pragma unroll
            for (int m = 0; m < 8; ++m) acc += sP[i][m] * sInv[m][j];
            g_M[t * 128 + tid] = acc;
            sM[i][j] = acc;
            {
                int di = __float_as_int(fabsf(acc - sMprev[i][j]));
                di = __reduce_max_sync(FULL, di);
                if ((tid & 31) == 0) atomicMax(&s_max, di);
            }
            sMprev[i][j] = acc;
        }
        __syncthreads();

        {
            float x1 = 0.f, x2 = 0.f;
            #pragma unroll
            for (int m = 0; m < 8; ++m) {
                x1 += sM[i16][m] * sP[j16][m];
                x2 += sM[j16][m] * sP[i16][m];
            }
            sS[i16][j16] = 0.5f * (sASA[i16][j16] + sASA[j16][i16])
                         - 0.5f * (x1 + x2);
        }
        if (tid == 0 && __int_as_float(s_max) < 4e-3f) s_done = 1;
        __syncthreads();
        if (s_done) { conv_t = t; break; }
    }

    if (tid == 0) g_conv = conv_t;
}

// =====================================================================
// prep: per chunk — freeze-fill tables, build G_t/atld_t, H_c, C_t,
// Q_c = sum C^T N C, ldc_c. One block per chunk.
// =====================================================================
__global__ void __launch_bounds__(256, 1)
prep_kernel(const float* __restrict__ A, const float* __restrict__ B,
            const float* __restrict__ a, const float* __restrict__ b)
{
    __shared__ float sM[16][8];
    __shared__ float sN[8][8];
    __shared__ float sB2[8][16];
    __shared__ float sG[16][16];
    __shared__ float sC[8][16];
    __shared__ float sT[8][16];
    __shared__ float sQm[16][16];
    __shared__ float sH[2][16][16];
    __shared__ float s_ld;
    int tid = threadIdx.x;
    int i = tid >> 4, k = tid & 15;
    int conv = g_conv;

    sH[0][i][k] = (i == k) ? 1.f : 0.f;
    sQm[i][k] = 0.f;
    float a_ik = A[tid];
    float Bcol[8];
    #pragma unroll
    for (int j = 0; j < 8; ++j) Bcol[j] = B[j * 16 + k];
    if (tid < 128) sB2[tid >> 4][tid & 15] = B[tid];
    if (tid == 255) s_ld = 0.f;
    int cur = 0;
    __syncthreads();

    for (int s = 0; s < CHUNKL; ++s) {
        int t = blockIdx.x * CHUNKL + s;
        int src = (t > conv) ? conv : t;
        if (tid < 128) {
            float mv = g_M[src * 128 + tid];
            if (t > conv) g_M[t * 128 + tid] = mv;
            sM[tid >> 3][tid & 7] = mv;
        } else if (tid < 192) {
            int id = tid - 128;
            float nv = g_Minv[src * 64 + id];
            if (t > conv) g_Minv[t * 64 + id] = nv;
            sN[id >> 3][id & 7] = nv;
        } else if (tid == 255) {
            float lv = g_logdet[src];
            if (t > conv) g_logdet[t] = lv;
            s_ld += lv;
        }
        __syncthreads();

        float gv = a_ik;
        #pragma unroll
        for (int j = 0; j < 8; ++j) gv -= sM[i][j] * Bcol[j];
        g_G[t * 256 + tid] = gv;
        sG[i][k] = gv;
        if (tid < 16) {
            float av = a[tid];
            #pragma unroll
            for (int j = 0; j < 8; ++j) av -= sM[tid][j] * b[j];
            g_atld[t * 16 + tid] = av;
        }
        if (tid < 128) {
            int j = tid >> 4, kk = tid & 15;
            float acc = 0.f;
            #pragma unroll
            for (int l = 0; l < 16; ++l) acc += sB2[j][l] * sH[cur][l][kk];
            sC[j][kk] = acc;
            g_C[t * 128 + tid] = acc;
        }
        __syncthreads();

        if (tid < 128) {
            int j = tid >> 4, kk = tid & 15;
            float acc = 0.f;
            #pragma unroll
            for (int m = 0; m < 8; ++m) acc += sN[j][m] * sC[m][kk];
            sT[j][kk] = acc;
        } else {
            #pragma unroll
            for (int e = tid - 128; e < 256; e += 128) {
                int i2 = e >> 4, k2 = e & 15;
                float acc = 0.f;
                #pragma unroll
                for (int l = 0; l < 16; ++l) acc += sG[i2][l] * sH[cur][l][k2];
                sH[cur ^ 1][i2][k2] = acc;
            }
        }
        __syncthreads();

        {
            float acc = 0.f;
            #pragma unroll
            for (int j = 0; j < 8; ++j) acc += sC[j][i] * sT[j][k];
            sQm[i][k] += acc;
        }
        cur ^= 1;
        __syncthreads();
    }
    g_H[blockIdx.x * 256 + tid] = sH[cur][i][k];
    g_Q[blockIdx.x * 256 + tid] = sQm[i][k];
    if (tid == 255) g_ldc[blockIdx.x] = s_ld;
}

// ---- depth-4 tree dot helpers -------------------------------------------
__device__ __forceinline__ float dot16_tree(float4 G0, float4 G1, float4 G2,
                                            float4 G3, const float* mu)
{
    float p0 = fmaf(G0.x, mu[0],  G0.y * mu[1]);
    float p1 = fmaf(G0.z, mu[2],  G0.w * mu[3]);
    float p2 = fmaf(G1.x, mu[4],  G1.y * mu[5]);
    float p3 = fmaf(G1.z, mu[6],  G1.w * mu[7]);
    float p4 = fmaf(G2.x, mu[8],  G2.y * mu[9]);
    float p5 = fmaf(G2.z, mu[10], G2.w * mu[11]);
    float p6 = fmaf(G3.x, mu[12], G3.y * mu[13]);
    float p7 = fmaf(G3.z, mu[14], G3.w * mu[15]);
    return ((p0 + p1) + (p2 + p3)) + ((p4 + p5) + (p6 + p7));
}
__device__ __forceinline__ float dot8_tree(float4 m0, float4 m1,
                                           float4 x0, float4 x1)
{
    float q0 = fmaf(m0.x, x0.x, m0.y * x0.y);
    float q1 = fmaf(m0.z, x0.z, m0.w * x0.w);
    float q2 = fmaf(m1.x, x1.x, m1.y * x1.y);
    float q3 = fmaf(m1.z, x1.z, m1.w * x1.w);
    return (q0 + q1) + (q2 + q3);
}

#define GP 20
#define MP 12

// =====================================================================
// Pass B: zero-init chunk responses + quadform accumulators.
// =====================================================================
__global__ void __launch_bounds__(256)
passB_kernel(const float* __restrict__ x, const float* __restrict__ b,
             const float* __restrict__ B)
{
    __shared__ __align__(16) float sG[CHUNKL * 16 * GP];
    __shared__ __align__(16) float sM[CHUNKL * 16 * MP];
    __shared__ __align__(16) float sC[CHUNKL * 128];
    __shared__ __align__(16) float sN[CHUNKL * 8 * MP];
    __shared__ float sat[CHUNKL * 16];

    const unsigned FULL = 0xffffffffu;
    int tid = threadIdx.x;
    int lane = tid & 31, warp = tid >> 5;
    int chunk = blockIdx.x >> 3, sub = blockIdx.x & 7;
    int g = lane >> 4, i = lane & 15;
    int b0 = sub * 32 + warp * 4 + g * 2;
    int t0 = chunk * CHUNKL;

    {
        const float4* srcG = (const float4*)(g_G + t0 * 256);
        #pragma unroll
        for (int q = 0; q < 4; ++q) {
            int idx = tid + q * 256;
            int s = idx >> 6, r = idx & 63, ii = r >> 2, qq = r & 3;
            *(float4*)(sG + (s * 16 + ii) * GP + qq * 4) = srcG[idx];
        }
        const float4* srcM = (const float4*)(g_M + t0 * 128);
        #pragma unroll
        for (int q = 0; q < 2; ++q) {
            int idx = tid + q * 256;
            int s = idx >> 5, r = idx & 31, ii = r >> 1, qq = r & 1;
            *(float4*)(sM + (s * 16 + ii) * MP + qq * 4) = srcM[idx];
        }
        const float4* srcC = (const float4*)(g_C + t0 * 128);
        #pragma unroll
        for (int q = 0; q < 2; ++q) {
            int idx = tid + q * 256;
            ((float4*)sC)[idx] = srcC[idx];
        }
        {
            const float4* srcN = (const float4*)(g_Minv + t0 * 64);
            int idx = tid;
            int s = idx >> 4, r = idx & 15, jj = r >> 1, qq = r & 1;
            *(float4*)(sN + (s * 8 + jj) * MP + qq * 4) = srcN[idx];
        }
        sat[tid] = g_atld[t0 * 16 + tid];
    }
    __syncthreads();

    float Brow[16];
    #pragma unroll
    for (int k = 0; k < 16; ++k) Brow[k] = (i < 8) ? B[i * 16 + k] : 0.f;
    float b_i = (i < 8) ? b[i] : 0.f;

    float mu0[16], mu1[16];
    #pragma unroll
    for (int k = 0; k < 16; ++k) { mu0[k] = 0.f; mu1[k] = 0.f; }
    float own0 = 0.f, own1 = 0.f;
    float sred0 = 0.f, sred1 = 0.f;
    float lv0 = 0.f, lv1 = 0.f;

    const float* xb0 = x + (size_t)b0 * T_LEN * 8;
    const float* xb1 = xb0 + T_LEN * 8;

    for (int s = 0; s < CHUNKL; ++s) {
        int t = t0 + s;
        float xv0 = (i < 8) ? xb0[t * 8 + i] : 0.f;
        float xv1 = (i < 8) ? xb1[t * 8 + i] : 0.f;
        float innov0 = xv0 - b_i - dot16_tree(*(const float4*)(Brow),
                                              *(const float4*)(Brow + 4),
                                              *(const float4*)(Brow + 8),
                                              *(const float4*)(Brow + 12), mu0);
        float innov1 = xv1 - b_i - dot16_tree(*(const float4*)(Brow),
                                              *(const float4*)(Brow + 4),
                                              *(const float4*)(Brow + 8),
                                              *(const float4*)(Brow + 12), mu1);

        float iva[8], ivb[8];
        #pragma unroll
        for (int j = 0; j < 8; ++j) {
            iva[j] = __shfl_sync(FULL, innov0, j, 16);
            ivb[j] = __shfl_sync(FULL, innov1, j, 16);
        }

        const float* Nr = sN + (s * 8 + (i & 7)) * MP;
        float4 n0 = *(const float4*)(Nr), n1 = *(const float4*)(Nr + 4);
        float qf0 = n0.x * iva[0] + n0.y * iva[1] + n0.z * iva[2] + n0.w * iva[3]
                  + n1.x * iva[4] + n1.y * iva[5] + n1.z * iva[6] + n1.w * iva[7];
        float qf1 = n0.x * ivb[0] + n0.y * ivb[1] + n0.z * ivb[2] + n0.w * ivb[3]
                  + n1.x * ivb[4] + n1.y * ivb[5] + n1.z * ivb[6] + n1.w * ivb[7];
        sred0 += (i < 8) ? innov0 * qf0 : 0.f;
        sred1 += (i < 8) ? innov1 * qf1 : 0.f;

        const float* Cs = sC + s * 128;
        #pragma unroll
        for (int j = 0; j < 8; ++j) {
            float qa = __shfl_sync(FULL, qf0, j, 16);
            float qb = __shfl_sync(FULL, qf1, j, 16);
            float cji = Cs[j * 16 + i];
            lv0 = fmaf(cji, qa, lv0);
            lv1 = fmaf(cji, qb, lv1);
        }

        const float* Gr = sG + (s * 16 + i) * GP;
        const float* Mr = sM + (s * 16 + i) * MP;
        float4 G0 = *(const float4*)(Gr),      G1 = *(const float4*)(Gr + 4);
        float4 G2 = *(const float4*)(Gr + 8),  G3 = *(const float4*)(Gr + 12);
        float4 m0 = *(const float4*)(Mr),      m1 = *(const float4*)(Mr + 4);
        float at = sat[s * 16 + i];
        const float4* xpa = (const float4*)(xb0 + t * 8);
        const float4* xpb = (const float4*)(xb1 + t * 8);
        float4 x0a = xpa[0], x1a = xpa[1];
        float4 x0b = xpb[0], x1b = xpb[1];

        float mn0 = at + dot16_tree(G0, G1, G2, G3, mu0) + dot8_tree(m0, m1, x0a, x1a);
        float mn1 = at + dot16_tree(G0, G1, G2, G3, mu1) + dot8_tree(m0, m1, x0b, x1b);
        own0 = mn0; own1 = mn1;
        #pragma unroll
        for (int k = 0; k < 16; ++k) {
            mu0[k] = __shfl_sync(FULL, mn0, k, 16);
            mu1[k] = __shfl_sync(FULL, mn1, k, 16);
        }
    }

    g_p[(chunk * NBATCH + b0)     * 16 + i] = own0;
    g_p[(chunk * NBATCH + b0 + 1) * 16 + i] = own1;
    g_l[(chunk * NBATCH + b0)     * 16 + i] = lv0;
    g_l[(chunk * NBATCH + b0 + 1) * 16 + i] = lv1;
    #pragma unroll
    for (int off = 1; off < 16; off <<= 1) {
        sred0 += __shfl_xor_sync(FULL, sred0, off, 16);
        sred1 += __shfl_xor_sync(FULL, sred1, off, 16);
    }
    if (i == 0) {
        g_cnst[chunk * NBATCH + b0]     = sred0;
        g_cnst[chunk * NBATCH + b0 + 1] = sred1;
    }
}

// =====================================================================
// Combine (UNFUSED, round-12 form): grid 128 x 32 thr, 8-deep ring.
// Scan chain only; writes g_mustart.
// =====================================================================
__global__ void __launch_bounds__(32, 1)
combine_kernel(const float* __restrict__ a0)
{
    const unsigned FULL = 0xffffffffu;
    int lane = threadIdx.x;
    int g = lane >> 4, i = lane & 15;
    int batch = blockIdx.x * 2 + g;

    float own = a0[i];
    float mu[16];
    #pragma unroll
    for (int k = 0; k < 16; ++k) mu[k] = __shfl_sync(FULL, own, k, 16);

    float4 h0[8], h1[8], h2[8], h3[8];
    float pv[8];
    #pragma unroll
    for (int d = 0; d < 8; ++d) {
        const float4* Hp = (const float4*)(g_H + d * 256 + i * 16);
        h0[d] = Hp[0]; h1[d] = Hp[1]; h2[d] = Hp[2]; h3[d] = Hp[3];
        pv[d] = g_p[(d * NBATCH + batch) * 16 + i];
    }

    #pragma unroll 8
    for (int c = 0; c < NCHUNK; ++c) {
        const int slot = c & 7;
        g_mustart[(c * NBATCH + batch) * 16 + i] = own;
        float mn = pv[slot] + dot16_tree(h0[slot], h1[slot], h2[slot], h3[slot], mu);
        int cn = c + 8;
        if (cn < NCHUNK) {
            const float4* Hp = (const float4*)(g_H + cn * 256 + i * 16);
            h0[slot] = Hp[0]; h1[slot] = Hp[1]; h2[slot] = Hp[2]; h3[slot] = Hp[3];
            pv[slot] = g_p[(cn * NBATCH + batch) * 16 + i];
        }
        own = mn;
        #pragma unroll
        for (int k = 0; k < 16; ++k) mu[k] = __shfl_sync(FULL, mn, k, 16);
    }
}

// =====================================================================
// eval (round-12 form): per-batch quadform evaluation + final sum.
// nll_b = 0.5 * sum_c [cnst - 2 lvec.mu_c + mu_c^T Q_c mu_c
//                      + ldc_c + 128*log2pi]
// =====================================================================
__global__ void __launch_bounds__(32, 1)
eval_kernel(float* __restrict__ out)
{
    const unsigned FULL = 0xffffffffu;
    const float LOG2PI = 1.8378770664093453f;
    int lane = threadIdx.x;
    int g = lane >> 4, i = lane & 15;
    int batch = blockIdx.x * 2 + g;

    float acc = 0.f;

    #pragma unroll 2
    for (int c = 0; c < NCHUNK; ++c) {
        float mo = g_mustart[(c * NBATCH + batch) * 16 + i];
        float lv = g_l[(c * NBATCH + batch) * 16 + i];
        float mu[16];
        #pragma unroll
        for (int k = 0; k < 16; ++k) mu[k] = __shfl_sync(FULL, mo, k, 16);
        const float4* Qp = (const float4*)(g_Q + c * 256 + i * 16);
        float4 q0 = Qp[0], q1 = Qp[1], q2 = Qp[2], q3 = Qp[3];
        float qi = dot16_tree(q0, q1, q2, q3, mu);
        acc += mo * (qi - 2.f * lv);
        if (i == (c & 15))
            acc += g_cnst[c * NBATCH + batch] + g_ldc[c] + 128.f * LOG2PI;
    }

    #pragma unroll
    for (int off = 1; off < 16; off <<= 1)
        acc += __shfl_xor_sync(FULL, acc, off, 16);
    if (i == 0) out[batch] = 0.5f * acc;
}

// =====================================================================
// Launcher
// =====================================================================
extern "C" void kernel_launch(void* const* d_in, const int* in_sizes, int n_in,
                              void* d_out, int out_size)
{
    const float* x  = (const float*)d_in[0];
    const float* a  = (const float*)d_in[1];
    const float* b  = (const float*)d_in[2];
    const float* A  = (const float*)d_in[3];
    const float* B  = (const float*)d_in[4];
    const float* U  = (const float*)d_in[5];
    const float* V  = (const float*)d_in[6];
    const float* W  = (const float*)d_in[7];
    const float* a0 = (const float*)d_in[8];
    const float* A0 = (const float*)d_in[9];
    float* out = (float*)d_out;

    riccati_kernel<<<1, 256>>>(A, B, U, V, W, A0);
    prep_kernel<<<NCHUNK, 256>>>(A, B, a, b);
    passB_kernel<<<NCHUNK * (NBATCH / 32), 256>>>(x, b, B);
    combine_kernel<<<NBATCH / 2, 32>>>(a0);
    eval_kernel<<<NBATCH / 2, 32>>>(out);
}

// round 15
// speedup vs baseline: 1.0679x; 1.0679x over previous
#include <cuda_runtime.h>
#include <math.h>

#define T_LEN   1024
#define NBATCH  256
#define NCHUNK  64
#define CHUNKL  16
#define RIC_CAP 256

// ---------------- device scratch (no allocations allowed) ----------------
__device__ __align__(16) float g_M[T_LEN * 128];       // M_t, [t][16][8]
__device__ __align__(16) float g_Minv[T_LEN * 64];     // inv(innov_var_t), [t][8][8]
__device__ __align__(16) float g_logdet[T_LEN];        // logdet(innov_var_t)
__device__ __align__(16) float g_C[T_LEN * 128];       // C_t = B*Phi_t, [t][8][16]
__device__ __align__(16) float g_Q[NCHUNK * 256];      // Q_c = sum C^T N C
__device__ __align__(16) float g_ldc[NCHUNK];          // per-chunk logdet sum
__device__ __align__(16) float g_H[NCHUNK * 256];      // chunk transition 16x16
__device__ __align__(16) float g_p[NCHUNK * NBATCH * 16];        // zero-init response
__device__ __align__(16) float g_l[NCHUNK * NBATCH * 16];        // lvec per batch-chunk
__device__ __align__(16) float g_cnst[NCHUNK * NBATCH];          // d^T N d sums
__device__ __align__(16) float g_mustart[NCHUNK * NBATCH * 16];  // chunk entry states
__device__ int g_conv;

// =====================================================================
// Phase 1: batch-independent Riccati. ΔM freeze threshold 4e-3.
// =====================================================================
__global__ void __launch_bounds__(256, 1)
riccati_kernel(const float* __restrict__ A, const float* __restrict__ B,
               const float* __restrict__ U, const float* __restrict__ V,
               const float* __restrict__ W, const float* __restrict__ A0)
{
    __shared__ float sS[16][16];
    __shared__ float sAS[16][16];
    __shared__ float sSBt[16][8];
    __shared__ float sR[8][8];
    __shared__ float sInv[8][8];
    __shared__ float sP[16][8];
    __shared__ float sASA[16][16];
    __shared__ float sM[16][8];
    __shared__ float sMprev[16][8];
    __shared__ float sA[16][16], sB[8][16], sQ[16][16], sV[8][8];
    __shared__ int s_max;
    __shared__ int s_done;

    const unsigned FULL = 0xffffffffu;
    const int tid = threadIdx.x;
    const int i16 = tid >> 4, j16 = tid & 15;

    sA[i16][j16] = A[tid];
    sS[i16][j16] = A0[tid];
    if (tid < 128) { sB[tid >> 4][tid & 15] = B[tid]; sMprev[tid >> 3][tid & 7] = 0.f; }
    if (tid < 64)  sV[tid >> 3][tid & 7]  = V[tid];
    if (tid == 0) { s_done = 0; s_max = 0; }
    __syncthreads();

    {
        float acc = 0.f;
        #pragma unroll
        for (int k = 0; k < 16; ++k) acc += W[i16 * 16 + k] * U[k * 16 + j16];
        sAS[i16][j16] = acc;
    }
    __syncthreads();
    {
        float acc = 0.f;
        #pragma unroll
        for (int k = 0; k < 16; ++k) acc += sAS[i16][k] * W[j16 * 16 + k];
        sQ[i16][j16] = acc;
    }
    __syncthreads();

    int conv_t = RIC_CAP - 1;

    for (int t = 0; t < RIC_CAP; ++t) {
        {
            float acc = 0.f;
            #pragma unroll
            for (int k = 0; k < 16; ++k) acc += sA[i16][k] * sS[k][j16];
            sAS[i16][j16] = acc;
        }
        if (tid < 128) {
            int i = tid >> 3, j = tid & 7;
            float acc = 0.f;
            #pragma unroll
            for (int k = 0; k < 16; ++k) acc += sS[i][k] * sB[j][k];
            sSBt[i][j] = acc;
        }
        __syncthreads();

        if (tid < 64) {
            int i = tid >> 3, j = tid & 7;
            float acc = sV[i][j];
            #pragma unroll
            for (int k = 0; k < 16; ++k) acc += sB[i][k] * sSBt[k][j];
            sR[i][j] = acc;
        } else if (tid < 192) {
            int id = tid - 64;
            int i = id >> 3, j = id & 7;
            float acc = 0.f;
            #pragma unroll
            for (int k = 0; k < 16; ++k) acc += sA[i][k] * sSBt[k][j];
            sP[i][j] = acc;
        } else {
            int id = tid - 192;
            int i = id >> 4, j = id & 15;
            float acc = sQ[i][j];
            #pragma unroll
            for (int k = 0; k < 16; ++k) acc += sAS[i][k] * sA[j][k];
            sASA[i][j] = acc;
            if (tid == 255) s_max = 0;
        }
        __syncthreads();

        if (tid < 32) {
            int lane = tid;
            int j = lane >> 2, cq = lane & 3;
            float v[4];
            if (cq < 2) {
                #pragma unroll
                for (int r = 0; r < 4; ++r) v[r] = sR[j][cq * 4 + r];
            } else {
                #pragma unroll
                for (int r = 0; r < 4; ++r)
                    v[r] = ((cq - 2) * 4 + r == j) ? 1.f : 0.f;
            }
            float prod = 1.f, mydiag = 1.f;
            #pragma unroll
            for (int k = 0; k < 8; ++k) {
                float pk = __shfl_sync(FULL, v[k & 3], (k << 2) | (k >> 2));
                float fk = __shfl_sync(FULL, v[k & 3], (lane & 28) | (k >> 2));
                float r0 = __shfl_sync(FULL, v[0], (k << 2) | cq);
                float r1 = __shfl_sync(FULL, v[1], (k << 2) | cq);
                float r2 = __shfl_sync(FULL, v[2], (k << 2) | cq);
                float r3 = __shfl_sync(FULL, v[3], (k << 2) | cq);
                if (j != k) {
                    float c = fk * __frcp_rn(pk);
                    v[0] = fmaf(-c, r0, v[0]);
                    v[1] = fmaf(-c, r1, v[1]);
                    v[2] = fmaf(-c, r2, v[2]);
                    v[3] = fmaf(-c, r3, v[3]);
                } else {
                    mydiag = pk;
                }
                prod *= pk;
            }
            float rd = __frcp_rn(mydiag);
            if (cq >= 2) {
                #pragma unroll
                for (int r = 0; r < 4; ++r) {
                    int c = (cq - 2) * 4 + r;
                    float iv = v[r] * rd;
                    sInv[j][c] = iv;
                    g_Minv[t * 64 + j * 8 + c] = iv;
                }
            }
            if (lane == 0) g_logdet[t] = __logf(prod);
        } else if (tid < 224) {
            int id = tid + 32;
            int i = id >> 4, j = id & 15;
            float acc = sQ[i][j];
            #pragma unroll
            for (int k = 0; k < 16; ++k) acc += sAS[i][k] * sA[j][k];
            sASA[i][j] = acc;
        }
        __syncthreads();

        if (tid < 128) {
            int i = tid >> 3, j = tid & 7;
            float acc = 0.f;
            #pragma unroll
            for (int m = 0; m < 8; ++m) acc += sP[i][m] * sInv[m][j];
            g_M[t * 128 + tid] = acc;
            sM[i][j] = acc;
            {
                int di = __float_as_int(fabsf(acc - sMprev[i][j]));
                di = __reduce_max_sync(FULL, di);
                if ((tid & 31) == 0) atomicMax(&s_max, di);
            }
            sMprev[i][j] = acc;
        }
        __syncthreads();

        {
            float x1 = 0.f, x2 = 0.f;
            #pragma unroll
            for (int m = 0; m < 8; ++m) {
                x1 += sM[i16][m] * sP[j16][m];
                x2 += sM[j16][m] * sP[i16][m];
            }
            sS[i16][j16] = 0.5f * (sASA[i16][j16] + sASA[j16][i16])
                         - 0.5f * (x1 + x2);
        }
        if (tid == 0 && __int_as_float(s_max) < 4e-3f) s_done = 1;
        __syncthreads();
        if (s_done) { conv_t = t; break; }
    }

    if (tid == 0) g_conv = conv_t;
}

// =====================================================================
// prep: per chunk — freeze-fill tables, build H_c, C_t, Q_c, ldc_c.
// (G kept only in smem for the H product; no g_G / g_atld tables.)
// =====================================================================
__global__ void __launch_bounds__(256, 1)
prep_kernel(const float* __restrict__ A, const float* __restrict__ B)
{
    __shared__ float sM[16][8];
    __shared__ float sN[8][8];
    __shared__ float sB2[8][16];
    __shared__ float sG[16][16];
    __shared__ float sC[8][16];
    __shared__ float sT[8][16];
    __shared__ float sQm[16][16];
    __shared__ float sH[2][16][16];
    __shared__ float s_ld;
    int tid = threadIdx.x;
    int i = tid >> 4, k = tid & 15;
    int conv = g_conv;

    sH[0][i][k] = (i == k) ? 1.f : 0.f;
    sQm[i][k] = 0.f;
    float a_ik = A[tid];
    float Bcol[8];
    #pragma unroll
    for (int j = 0; j < 8; ++j) Bcol[j] = B[j * 16 + k];
    if (tid < 128) sB2[tid >> 4][tid & 15] = B[tid];
    if (tid == 255) s_ld = 0.f;
    int cur = 0;
    __syncthreads();

    for (int s = 0; s < CHUNKL; ++s) {
        int t = blockIdx.x * CHUNKL + s;
        int src = (t > conv) ? conv : t;
        if (tid < 128) {
            float mv = g_M[src * 128 + tid];
            if (t > conv) g_M[t * 128 + tid] = mv;
            sM[tid >> 3][tid & 7] = mv;
        } else if (tid < 192) {
            int id = tid - 128;
            float nv = g_Minv[src * 64 + id];
            if (t > conv) g_Minv[t * 64 + id] = nv;
            sN[id >> 3][id & 7] = nv;
        } else if (tid == 255) {
            float lv = g_logdet[src];
            if (t > conv) g_logdet[t] = lv;
            s_ld += lv;
        }
        __syncthreads();

        float gv = a_ik;
        #pragma unroll
        for (int j = 0; j < 8; ++j) gv -= sM[i][j] * Bcol[j];
        sG[i][k] = gv;
        if (tid < 128) {
            int j = tid >> 4, kk = tid & 15;
            float acc = 0.f;
            #pragma unroll
            for (int l = 0; l < 16; ++l) acc += sB2[j][l] * sH[cur][l][kk];
            sC[j][kk] = acc;
            g_C[t * 128 + tid] = acc;
        }
        __syncthreads();

        if (tid < 128) {
            int j = tid >> 4, kk = tid & 15;
            float acc = 0.f;
            #pragma unroll
            for (int m = 0; m < 8; ++m) acc += sN[j][m] * sC[m][kk];
            sT[j][kk] = acc;
        } else {
            #pragma unroll
            for (int e = tid - 128; e < 256; e += 128) {
                int i2 = e >> 4, k2 = e & 15;
                float acc = 0.f;
                #pragma unroll
                for (int l = 0; l < 16; ++l) acc += sG[i2][l] * sH[cur][l][k2];
                sH[cur ^ 1][i2][k2] = acc;
            }
        }
        __syncthreads();

        {
            float acc = 0.f;
            #pragma unroll
            for (int j = 0; j < 8; ++j) acc += sC[j][i] * sT[j][k];
            sQm[i][k] += acc;
        }
        cur ^= 1;
        __syncthreads();
    }
    g_H[blockIdx.x * 256 + tid] = sH[cur][i][k];
    g_Q[blockIdx.x * 256 + tid] = sQm[i][k];
    if (tid == 255) g_ldc[blockIdx.x] = s_ld;
}

// ---- depth-4 tree dot helpers -------------------------------------------
__device__ __forceinline__ float dot16_tree(float4 G0, float4 G1, float4 G2,
                                            float4 G3, const float* mu)
{
    float p0 = fmaf(G0.x, mu[0],  G0.y * mu[1]);
    float p1 = fmaf(G0.z, mu[2],  G0.w * mu[3]);
    float p2 = fmaf(G1.x, mu[4],  G1.y * mu[5]);
    float p3 = fmaf(G1.z, mu[6],  G1.w * mu[7]);
    float p4 = fmaf(G2.x, mu[8],  G2.y * mu[9]);
    float p5 = fmaf(G2.z, mu[10], G2.w * mu[11]);
    float p6 = fmaf(G3.x, mu[12], G3.y * mu[13]);
    float p7 = fmaf(G3.z, mu[14], G3.w * mu[15]);
    return ((p0 + p1) + (p2 + p3)) + ((p4 + p5) + (p6 + p7));
}
__device__ __forceinline__ float dot16_regs(const float* w, const float* mu)
{
    float p0 = fmaf(w[0],  mu[0],  w[1]  * mu[1]);
    float p1 = fmaf(w[2],  mu[2],  w[3]  * mu[3]);
    float p2 = fmaf(w[4],  mu[4],  w[5]  * mu[5]);
    float p3 = fmaf(w[6],  mu[6],  w[7]  * mu[7]);
    float p4 = fmaf(w[8],  mu[8],  w[9]  * mu[9]);
    float p5 = fmaf(w[10], mu[10], w[11] * mu[11]);
    float p6 = fmaf(w[12], mu[12], w[13] * mu[13]);
    float p7 = fmaf(w[14], mu[14], w[15] * mu[15]);
    return ((p0 + p1) + (p2 + p3)) + ((p4 + p5) + (p6 + p7));
}

#define MP 12

// =====================================================================
// Pass B (A-form): zero-init chunk responses + quadform accumulators.
// mu' = a + A*mu + M*innov, with innov already computed for the quadform.
// smem: only M (12KB) + C (8KB) + Minv (6KB). x touched 1 scalar/lane.
// =====================================================================
__global__ void __launch_bounds__(256)
passB_kernel(const float* __restrict__ x, const float* __restrict__ a,
             const float* __restrict__ b, const float* __restrict__ A,
             const float* __restrict__ B)
{
    __shared__ __align__(16) float sM[CHUNKL * 16 * MP];   // 12 KB
    __shared__ __align__(16) float sC[CHUNKL * 128];       // 8 KB
    __shared__ __align__(16) float sN[CHUNKL * 8 * MP];    // 6 KB

    const unsigned FULL = 0xffffffffu;
    int tid = threadIdx.x;
    int lane = tid & 31, warp = tid >> 5;
    int chunk = blockIdx.x >> 3, sub = blockIdx.x & 7;
    int g = lane >> 4, i = lane & 15;
    int b0 = sub * 32 + warp * 4 + g * 2;
    int t0 = chunk * CHUNKL;

    {
        const float4* srcM = (const float4*)(g_M + t0 * 128);
        #pragma unroll
        for (int q = 0; q < 2; ++q) {
            int idx = tid + q * 256;
            int s = idx >> 5, r = idx & 31, ii = r >> 1, qq = r & 1;
            *(float4*)(sM + (s * 16 + ii) * MP + qq * 4) = srcM[idx];
        }
        const float4* srcC = (const float4*)(g_C + t0 * 128);
        #pragma unroll
        for (int q = 0; q < 2; ++q) {
            int idx = tid + q * 256;
            ((float4*)sC)[idx] = srcC[idx];
        }
        {
            const float4* srcN = (const float4*)(g_Minv + t0 * 64);
            int idx = tid;
            int s = idx >> 4, r = idx & 15, jj = r >> 1, qq = r & 1;
            *(float4*)(sN + (s * 8 + jj) * MP + qq * 4) = srcN[idx];
        }
    }
    __syncthreads();

    float Arow[16], Brow[16];
    #pragma unroll
    for (int k = 0; k < 16; ++k) Arow[k] = A[i * 16 + k];
    #pragma unroll
    for (int k = 0; k < 16; ++k) Brow[k] = (i < 8) ? B[i * 16 + k] : 0.f;
    float a_i = a[i];
    float b_i = (i < 8) ? b[i] : 0.f;

    float mu0[16], mu1[16];
    #pragma unroll
    for (int k = 0; k < 16; ++k) { mu0[k] = 0.f; mu1[k] = 0.f; }
    float own0 = 0.f, own1 = 0.f;
    float sred0 = 0.f, sred1 = 0.f;
    float lv0 = 0.f, lv1 = 0.f;

    const float* xb0 = x + (size_t)b0 * T_LEN * 8;
    const float* xb1 = xb0 + T_LEN * 8;

    for (int s = 0; s < CHUNKL; ++s) {
        int t = t0 + s;
        // ---- innovation (pre-update mu) ----
        float xv0 = (i < 8) ? xb0[t * 8 + i] : 0.f;
        float xv1 = (i < 8) ? xb1[t * 8 + i] : 0.f;
        float innov0 = xv0 - b_i - dot16_regs(Brow, mu0);
        float innov1 = xv1 - b_i - dot16_regs(Brow, mu1);

        float iva[8], ivb[8];
        #pragma unroll
        for (int j = 0; j < 8; ++j) {
            iva[j] = __shfl_sync(FULL, innov0, j, 16);
            ivb[j] = __shfl_sync(FULL, innov1, j, 16);
        }

        // qf = (N d)_row(i&7)
        const float* Nr = sN + (s * 8 + (i & 7)) * MP;
        float4 n0 = *(const float4*)(Nr), n1 = *(const float4*)(Nr + 4);
        float qf0 = n0.x * iva[0] + n0.y * iva[1] + n0.z * iva[2] + n0.w * iva[3]
                  + n1.x * iva[4] + n1.y * iva[5] + n1.z * iva[6] + n1.w * iva[7];
        float qf1 = n0.x * ivb[0] + n0.y * ivb[1] + n0.z * ivb[2] + n0.w * ivb[3]
                  + n1.x * ivb[4] + n1.y * ivb[5] + n1.z * ivb[6] + n1.w * ivb[7];
        sred0 += (i < 8) ? innov0 * qf0 : 0.f;
        sred1 += (i < 8) ? innov1 * qf1 : 0.f;

        // lvec_i += sum_j C[j][i] * (N d)_j
        const float* Cs = sC + s * 128;
        #pragma unroll
        for (int j = 0; j < 8; ++j) {
            float qa = __shfl_sync(FULL, qf0, j, 16);
            float qb = __shfl_sync(FULL, qf1, j, 16);
            float cji = Cs[j * 16 + i];
            lv0 = fmaf(cji, qa, lv0);
            lv1 = fmaf(cji, qb, lv1);
        }

        // ---- mu update (A-form): mu' = a + A*mu + M*innov ----
        const float* Mr = sM + (s * 16 + i) * MP;
        float4 m0 = *(const float4*)(Mr), m1 = *(const float4*)(Mr + 4);
        float mi0 = m0.x * iva[0] + m0.y * iva[1] + m0.z * iva[2] + m0.w * iva[3]
                  + m1.x * iva[4] + m1.y * iva[5] + m1.z * iva[6] + m1.w * iva[7];
        float mi1 = m0.x * ivb[0] + m0.y * ivb[1] + m0.z * ivb[2] + m0.w * ivb[3]
                  + m1.x * ivb[4] + m1.y * ivb[5] + m1.z * ivb[6] + m1.w * ivb[7];
        float mn0 = a_i + dot16_regs(Arow, mu0) + mi0;
        float mn1 = a_i + dot16_regs(Arow, mu1) + mi1;
        own0 = mn0; own1 = mn1;
        #pragma unroll
        for (int k = 0; k < 16; ++k) {
            mu0[k] = __shfl_sync(FULL, mn0, k, 16);
            mu1[k] = __shfl_sync(FULL, mn1, k, 16);
        }
    }

    g_p[(chunk * NBATCH + b0)     * 16 + i] = own0;
    g_p[(chunk * NBATCH + b0 + 1) * 16 + i] = own1;
    g_l[(chunk * NBATCH + b0)     * 16 + i] = lv0;
    g_l[(chunk * NBATCH + b0 + 1) * 16 + i] = lv1;
    #pragma unroll
    for (int off = 1; off < 16; off <<= 1) {
        sred0 += __shfl_xor_sync(FULL, sred0, off, 16);
        sred1 += __shfl_xor_sync(FULL, sred1, off, 16);
    }
    if (i == 0) {
        g_cnst[chunk * NBATCH + b0]     = sred0;
        g_cnst[chunk * NBATCH + b0 + 1] = sred1;
    }
}

// =====================================================================
// Combine: grid 128 x 32 thr, 8-deep ring. Scan chain only.
// =====================================================================
__global__ void __launch_bounds__(32, 1)
combine_kernel(const float* __restrict__ a0)
{
    const unsigned FULL = 0xffffffffu;
    int lane = threadIdx.x;
    int g = lane >> 4, i = lane & 15;
    int batch = blockIdx.x * 2 + g;

    float own = a0[i];
    float mu[16];
    #pragma unroll
    for (int k = 0; k < 16; ++k) mu[k] = __shfl_sync(FULL, own, k, 16);

    float4 h0[8], h1[8], h2[8], h3[8];
    float pv[8];
    #pragma unroll
    for (int d = 0; d < 8; ++d) {
        const float4* Hp = (const float4*)(g_H + d * 256 + i * 16);
        h0[d] = Hp[0]; h1[d] = Hp[1]; h2[d] = Hp[2]; h3[d] = Hp[3];
        pv[d] = g_p[(d * NBATCH + batch) * 16 + i];
    }

    #pragma unroll 8
    for (int c = 0; c < NCHUNK; ++c) {
        const int slot = c & 7;
        g_mustart[(c * NBATCH + batch) * 16 + i] = own;
        float mn = pv[slot] + dot16_tree(h0[slot], h1[slot], h2[slot], h3[slot], mu);
        int cn = c + 8;
        if (cn < NCHUNK) {
            const float4* Hp = (const float4*)(g_H + cn * 256 + i * 16);
            h0[slot] = Hp[0]; h1[slot] = Hp[1]; h2[slot] = Hp[2]; h3[slot] = Hp[3];
            pv[slot] = g_p[(cn * NBATCH + batch) * 16 + i];
        }
        own = mn;
        #pragma unroll
        for (int k = 0; k < 16; ++k) mu[k] = __shfl_sync(FULL, mn, k, 16);
    }
}

// =====================================================================
// eval: per-batch quadform evaluation + final sum.
// =====================================================================
__global__ void __launch_bounds__(32, 1)
eval_kernel(float* __restrict__ out)
{
    const unsigned FULL = 0xffffffffu;
    const float LOG2PI = 1.8378770664093453f;
    int lane = threadIdx.x;
    int g = lane >> 4, i = lane & 15;
    int batch = blockIdx.x * 2 + g;

    float acc = 0.f;

    #pragma unroll 2
    for (int c = 0; c < NCHUNK; ++c) {
        float mo = g_mustart[(c * NBATCH + batch) * 16 + i];
        float lv = g_l[(c * NBATCH + batch) * 16 + i];
        float mu[16];
        #pragma unroll
        for (int k = 0; k < 16; ++k) mu[k] = __shfl_sync(FULL, mo, k, 16);
        const float4* Qp = (const float4*)(g_Q + c * 256 + i * 16);
        float4 q0 = Qp[0], q1 = Qp[1], q2 = Qp[2], q3 = Qp[3];
        float qi = dot16_tree(q0, q1, q2, q3, mu);
        acc += mo * (qi - 2.f * lv);
        if (i == (c & 15))
            acc += g_cnst[c * NBATCH + batch] + g_ldc[c] + 128.f * LOG2PI;
    }

    #pragma unroll
    for (int off = 1; off < 16; off <<= 1)
        acc += __shfl_xor_sync(FULL, acc, off, 16);
    if (i == 0) out[batch] = 0.5f * acc;
}

// =====================================================================
// Launcher
// =====================================================================
extern "C" void kernel_launch(void* const* d_in, const int* in_sizes, int n_in,
                              void* d_out, int out_size)
{
    const float* x  = (const float*)d_in[0];
    const float* a  = (const float*)d_in[1];
    const float* b  = (const float*)d_in[2];
    const float* A  = (const float*)d_in[3];
    const float* B  = (const float*)d_in[4];
    const float* U  = (const float*)d_in[5];
    const float* V  = (const float*)d_in[6];
    const float* W  = (const float*)d_in[7];
    const float* a0 = (const float*)d_in[8];
    const float* A0 = (const float*)d_in[9];
    float* out = (float*)d_out;

    riccati_kernel<<<1, 256>>>(A, B, U, V, W, A0);
    prep_kernel<<<NCHUNK, 256>>>(A, B);
    passB_kernel<<<NCHUNK * (NBATCH / 32), 256>>>(x, a, b, A, B);
    combine_kernel<<<NBATCH / 2, 32>>>(a0);
    eval_kernel<<<NBATCH / 2, 32>>>(out);
}

// round 16
// speedup vs baseline: 1.0835x; 1.0146x over previous
#include <cuda_runtime.h>
#include <math.h>

#define T_LEN   1024
#define NBATCH  256
#define NCHUNK  64
#define CHUNKL  16
#define NSUPER  8
#define RIC_CAP 256

// ---------------- device scratch (no allocations allowed) ----------------
__device__ __align__(16) float g_M[T_LEN * 128];       // M_t, [t][16][8]
__device__ __align__(16) float g_Minv[T_LEN * 64];     // inv(innov_var_t), [t][8][8]
__device__ __align__(16) float g_logdet[T_LEN];        // logdet(innov_var_t)
__device__ __align__(16) float g_C[T_LEN * 128];       // C_t = B*Phi_t, [t][8][16]
__device__ __align__(16) float g_Q[NCHUNK * 256];      // Q_c = sum C^T N C
__device__ __align__(16) float g_ldc[NCHUNK];          // per-chunk logdet sum
__device__ __align__(16) float g_H[NCHUNK * 256];      // chunk transition 16x16
__device__ __align__(16) float g_HH[NSUPER * 256];     // super-chunk transitions
__device__ __align__(16) float g_p[NCHUNK * NBATCH * 16];        // zero-init response
__device__ __align__(16) float g_l[NCHUNK * NBATCH * 16];        // lvec per batch-chunk
__device__ __align__(16) float g_cnst[NCHUNK * NBATCH];          // d^T N d sums
__device__ __align__(16) float g_mustart[NCHUNK * NBATCH * 16];  // chunk entry states
__device__ int g_conv;

// =====================================================================
// Phase 1: batch-independent Riccati. ΔM freeze threshold 6e-3.
// =====================================================================
__global__ void __launch_bounds__(256, 1)
riccati_kernel(const float* __restrict__ A, const float* __restrict__ B,
               const float* __restrict__ U, const float* __restrict__ V,
               const float* __restrict__ W, const float* __restrict__ A0)
{
    __shared__ float sS[16][16];
    __shared__ float sAS[16][16];
    __shared__ float sSBt[16][8];
    __shared__ float sR[8][8];
    __shared__ float sInv[8][8];
    __shared__ float sP[16][8];
    __shared__ float sASA[16][16];
    __shared__ float sM[16][8];
    __shared__ float sMprev[16][8];
    __shared__ float sA[16][16], sB[8][16], sQ[16][16], sV[8][8];
    __shared__ int s_max;
    __shared__ int s_done;

    const unsigned FULL = 0xffffffffu;
    const int tid = threadIdx.x;
    const int i16 = tid >> 4, j16 = tid & 15;

    sA[i16][j16] = A[tid];
    sS[i16][j16] = A0[tid];
    if (tid < 128) { sB[tid >> 4][tid & 15] = B[tid]; sMprev[tid >> 3][tid & 7] = 0.f; }
    if (tid < 64)  sV[tid >> 3][tid & 7]  = V[tid];
    if (tid == 0) { s_done = 0; s_max = 0; }
    __syncthreads();

    {
        float acc = 0.f;
        #pragma unroll
        for (int k = 0; k < 16; ++k) acc += W[i16 * 16 + k] * U[k * 16 + j16];
        sAS[i16][j16] = acc;
    }
    __syncthreads();
    {
        float acc = 0.f;
        #pragma unroll
        for (int k = 0; k < 16; ++k) acc += sAS[i16][k] * W[j16 * 16 + k];
        sQ[i16][j16] = acc;
    }
    __syncthreads();

    int conv_t = RIC_CAP - 1;

    for (int t = 0; t < RIC_CAP; ++t) {
        {
            float acc = 0.f;
            #pragma unroll
            for (int k = 0; k < 16; ++k) acc += sA[i16][k] * sS[k][j16];
            sAS[i16][j16] = acc;
        }
        if (tid < 128) {
            int i = tid >> 3, j = tid & 7;
            float acc = 0.f;
            #pragma unroll
            for (int k = 0; k < 16; ++k) acc += sS[i][k] * sB[j][k];
            sSBt[i][j] = acc;
        }
        __syncthreads();

        if (tid < 64) {
            int i = tid >> 3, j = tid & 7;
            float acc = sV[i][j];
            #pragma unroll
            for (int k = 0; k < 16; ++k) acc += sB[i][k] * sSBt[k][j];
            sR[i][j] = acc;
        } else if (tid < 192) {
            int id = tid - 64;
            int i = id >> 3, j = id & 7;
            float acc = 0.f;
            #pragma unroll
            for (int k = 0; k < 16; ++k) acc += sA[i][k] * sSBt[k][j];
            sP[i][j] = acc;
        } else {
            int id = tid - 192;
            int i = id >> 4, j = id & 15;
            float acc = sQ[i][j];
            #pragma unroll
            for (int k = 0; k < 16; ++k) acc += sAS[i][k] * sA[j][k];
            sASA[i][j] = acc;
            if (tid == 255) s_max = 0;
        }
        __syncthreads();

        if (tid < 32) {
            int lane = tid;
            int j = lane >> 2, cq = lane & 3;
            float v[4];
            if (cq < 2) {
                #pragma unroll
                for (int r = 0; r < 4; ++r) v[r] = sR[j][cq * 4 + r];
            } else {
                #pragma unroll
                for (int r = 0; r < 4; ++r)
                    v[r] = ((cq - 2) * 4 + r == j) ? 1.f : 0.f;
            }
            float prod = 1.f, mydiag = 1.f;
            #pragma unroll
            for (int k = 0; k < 8; ++k) {
                float pk = __shfl_sync(FULL, v[k & 3], (k << 2) | (k >> 2));
                float fk = __shfl_sync(FULL, v[k & 3], (lane & 28) | (k >> 2));
                float r0 = __shfl_sync(FULL, v[0], (k << 2) | cq);
                float r1 = __shfl_sync(FULL, v[1], (k << 2) | cq);
                float r2 = __shfl_sync(FULL, v[2], (k << 2) | cq);
                float r3 = __shfl_sync(FULL, v[3], (k << 2) | cq);
                if (j != k) {
                    float c = fk * __frcp_rn(pk);
                    v[0] = fmaf(-c, r0, v[0]);
                    v[1] = fmaf(-c, r1, v[1]);
                    v[2] = fmaf(-c, r2, v[2]);
                    v[3] = fmaf(-c, r3, v[3]);
                } else {
                    mydiag = pk;
                }
                prod *= pk;
            }
            float rd = __frcp_rn(mydiag);
            if (cq >= 2) {
                #pragma unroll
                for (int r = 0; r < 4; ++r) {
                    int c = (cq - 2) * 4 + r;
                    float iv = v[r] * rd;
                    sInv[j][c] = iv;
                    g_Minv[t * 64 + j * 8 + c] = iv;
                }
            }
            if (lane == 0) g_logdet[t] = __logf(prod);
        } else if (tid < 224) {
            int id = tid + 32;
            int i = id >> 4, j = id & 15;
            float acc = sQ[i][j];
            #pragma unroll
            for (int k = 0; k < 16; ++k) acc += sAS[i][k] * sA[j][k];
            sASA[i][j] = acc;
        }
        __syncthreads();

        if (tid < 128) {
            int i = tid >> 3, j = tid & 7;
            float acc = 0.f;
            #pragma unroll
            for (int m = 0; m < 8; ++m) acc += sP[i][m] * sInv[m][j];
            g_M[t * 128 + tid] = acc;
            sM[i][j] = acc;
            {
                int di = __float_as_int(fabsf(acc - sMprev[i][j]));
                di = __reduce_max_sync(FULL, di);
                if ((tid & 31) == 0) atomicMax(&s_max, di);
            }
            sMprev[i][j] = acc;
        }
        __syncthreads();

        {
            float x1 = 0.f, x2 = 0.f;
            #pragma unroll
            for (int m = 0; m < 8; ++m) {
                x1 += sM[i16][m] * sP[j16][m];
                x2 += sM[j16][m] * sP[i16][m];
            }
            sS[i16][j16] = 0.5f * (sASA[i16][j16] + sASA[j16][i16])
                         - 0.5f * (x1 + x2);
        }
        if (tid == 0 && __int_as_float(s_max) < 6e-3f) s_done = 1;
        __syncthreads();
        if (s_done) { conv_t = t; break; }
    }

    if (tid == 0) g_conv = conv_t;
}

// =====================================================================
// prep: per chunk — freeze-fill tables, build H_c, C_t, Q_c, ldc_c.
// =====================================================================
__global__ void __launch_bounds__(256, 1)
prep_kernel(const float* __restrict__ A, const float* __restrict__ B)
{
    __shared__ float sM[16][8];
    __shared__ float sN[8][8];
    __shared__ float sB2[8][16];
    __shared__ float sG[16][16];
    __shared__ float sC[8][16];
    __shared__ float sT[8][16];
    __shared__ float sQm[16][16];
    __shared__ float sH[2][16][16];
    __shared__ float s_ld;
    int tid = threadIdx.x;
    int i = tid >> 4, k = tid & 15;
    int conv = g_conv;

    sH[0][i][k] = (i == k) ? 1.f : 0.f;
    sQm[i][k] = 0.f;
    float a_ik = A[tid];
    float Bcol[8];
    #pragma unroll
    for (int j = 0; j < 8; ++j) Bcol[j] = B[j * 16 + k];
    if (tid < 128) sB2[tid >> 4][tid & 15] = B[tid];
    if (tid == 255) s_ld = 0.f;
    int cur = 0;
    __syncthreads();

    for (int s = 0; s < CHUNKL; ++s) {
        int t = blockIdx.x * CHUNKL + s;
        int src = (t > conv) ? conv : t;
        if (tid < 128) {
            float mv = g_M[src * 128 + tid];
            if (t > conv) g_M[t * 128 + tid] = mv;
            sM[tid >> 3][tid & 7] = mv;
        } else if (tid < 192) {
            int id = tid - 128;
            float nv = g_Minv[src * 64 + id];
            if (t > conv) g_Minv[t * 64 + id] = nv;
            sN[id >> 3][id & 7] = nv;
        } else if (tid == 255) {
            float lv = g_logdet[src];
            if (t > conv) g_logdet[t] = lv;
            s_ld += lv;
        }
        __syncthreads();

        float gv = a_ik;
        #pragma unroll
        for (int j = 0; j < 8; ++j) gv -= sM[i][j] * Bcol[j];
        sG[i][k] = gv;
        if (tid < 128) {
            int j = tid >> 4, kk = tid & 15;
            float acc = 0.f;
            #pragma unroll
            for (int l = 0; l < 16; ++l) acc += sB2[j][l] * sH[cur][l][kk];
            sC[j][kk] = acc;
            g_C[t * 128 + tid] = acc;
        }
        __syncthreads();

        if (tid < 128) {
            int j = tid >> 4, kk = tid & 15;
            float acc = 0.f;
            #pragma unroll
            for (int m = 0; m < 8; ++m) acc += sN[j][m] * sC[m][kk];
            sT[j][kk] = acc;
        } else {
            #pragma unroll
            for (int e = tid - 128; e < 256; e += 128) {
                int i2 = e >> 4, k2 = e & 15;
                float acc = 0.f;
                #pragma unroll
                for (int l = 0; l < 16; ++l) acc += sG[i2][l] * sH[cur][l][k2];
                sH[cur ^ 1][i2][k2] = acc;
            }
        }
        __syncthreads();

        {
            float acc = 0.f;
            #pragma unroll
            for (int j = 0; j < 8; ++j) acc += sC[j][i] * sT[j][k];
            sQm[i][k] += acc;
        }
        cur ^= 1;
        __syncthreads();
    }
    g_H[blockIdx.x * 256 + tid] = sH[cur][i][k];
    g_Q[blockIdx.x * 256 + tid] = sQm[i][k];
    if (tid == 255) g_ldc[blockIdx.x] = s_ld;
}

// =====================================================================
// hierH: super-chunk transitions HH_s = H_{8s+7} ... H_{8s}.
// 8 blocks x 256 thr; 7 sequential 16x16 matmuls each.
// =====================================================================
__global__ void __launch_bounds__(256, 1)
hierH_kernel()
{
    __shared__ float sAcc[2][16][16];
    int tid = threadIdx.x;
    int i = tid >> 4, k = tid & 15;
    int c0 = blockIdx.x * 8;

    sAcc[0][i][k] = g_H[c0 * 256 + tid];
    __syncthreads();
    int cur = 0;
    for (int c = 1; c < 8; ++c) {
        const float* Hr = g_H + (c0 + c) * 256 + i * 16;
        float acc = 0.f;
        #pragma unroll
        for (int l = 0; l < 16; ++l) acc += Hr[l] * sAcc[cur][l][k];
        sAcc[cur ^ 1][i][k] = acc;
        cur ^= 1;
        __syncthreads();
    }
    g_HH[blockIdx.x * 256 + tid] = sAcc[cur][i][k];
}

// ---- depth-4 tree dot helpers -------------------------------------------
__device__ __forceinline__ float dot16_tree(float4 G0, float4 G1, float4 G2,
                                            float4 G3, const float* mu)
{
    float p0 = fmaf(G0.x, mu[0],  G0.y * mu[1]);
    float p1 = fmaf(G0.z, mu[2],  G0.w * mu[3]);
    float p2 = fmaf(G1.x, mu[4],  G1.y * mu[5]);
    float p3 = fmaf(G1.z, mu[6],  G1.w * mu[7]);
    float p4 = fmaf(G2.x, mu[8],  G2.y * mu[9]);
    float p5 = fmaf(G2.z, mu[10], G2.w * mu[11]);
    float p6 = fmaf(G3.x, mu[12], G3.y * mu[13]);
    float p7 = fmaf(G3.z, mu[14], G3.w * mu[15]);
    return ((p0 + p1) + (p2 + p3)) + ((p4 + p5) + (p6 + p7));
}
__device__ __forceinline__ float dot16_regs(const float* w, const float* mu)
{
    float p0 = fmaf(w[0],  mu[0],  w[1]  * mu[1]);
    float p1 = fmaf(w[2],  mu[2],  w[3]  * mu[3]);
    float p2 = fmaf(w[4],  mu[4],  w[5]  * mu[5]);
    float p3 = fmaf(w[6],  mu[6],  w[7]  * mu[7]);
    float p4 = fmaf(w[8],  mu[8],  w[9]  * mu[9]);
    float p5 = fmaf(w[10], mu[10], w[11] * mu[11]);
    float p6 = fmaf(w[12], mu[12], w[13] * mu[13]);
    float p7 = fmaf(w[14], mu[14], w[15] * mu[15]);
    return ((p0 + p1) + (p2 + p3)) + ((p4 + p5) + (p6 + p7));
}

#define MP 12

// =====================================================================
// Pass B (A-form): zero-init chunk responses + quadform accumulators.
// =====================================================================
__global__ void __launch_bounds__(256)
passB_kernel(const float* __restrict__ x, const float* __restrict__ a,
             const float* __restrict__ b, const float* __restrict__ A,
             const float* __restrict__ B)
{
    __shared__ __align__(16) float sM[CHUNKL * 16 * MP];   // 12 KB
    __shared__ __align__(16) float sC[CHUNKL * 128];       // 8 KB
    __shared__ __align__(16) float sN[CHUNKL * 8 * MP];    // 6 KB

    const unsigned FULL = 0xffffffffu;
    int tid = threadIdx.x;
    int lane = tid & 31, warp = tid >> 5;
    int chunk = blockIdx.x >> 3, sub = blockIdx.x & 7;
    int g = lane >> 4, i = lane & 15;
    int b0 = sub * 32 + warp * 4 + g * 2;
    int t0 = chunk * CHUNKL;

    {
        const float4* srcM = (const float4*)(g_M + t0 * 128);
        #pragma unroll
        for (int q = 0; q < 2; ++q) {
            int idx = tid + q * 256;
            int s = idx >> 5, r = idx & 31, ii = r >> 1, qq = r & 1;
            *(float4*)(sM + (s * 16 + ii) * MP + qq * 4) = srcM[idx];
        }
        const float4* srcC = (const float4*)(g_C + t0 * 128);
        #pragma unroll
        for (int q = 0; q < 2; ++q) {
            int idx = tid + q * 256;
            ((float4*)sC)[idx] = srcC[idx];
        }
        {
            const float4* srcN = (const float4*)(g_Minv + t0 * 64);
            int idx = tid;
            int s = idx >> 4, r = idx & 15, jj = r >> 1, qq = r & 1;
            *(float4*)(sN + (s * 8 + jj) * MP + qq * 4) = srcN[idx];
        }
    }
    __syncthreads();

    float Arow[16], Brow[16];
    #pragma unroll
    for (int k = 0; k < 16; ++k) Arow[k] = A[i * 16 + k];
    #pragma unroll
    for (int k = 0; k < 16; ++k) Brow[k] = (i < 8) ? B[i * 16 + k] : 0.f;
    float a_i = a[i];
    float b_i = (i < 8) ? b[i] : 0.f;

    float mu0[16], mu1[16];
    #pragma unroll
    for (int k = 0; k < 16; ++k) { mu0[k] = 0.f; mu1[k] = 0.f; }
    float own0 = 0.f, own1 = 0.f;
    float sred0 = 0.f, sred1 = 0.f;
    float lv0 = 0.f, lv1 = 0.f;

    const float* xb0 = x + (size_t)b0 * T_LEN * 8;
    const float* xb1 = xb0 + T_LEN * 8;

    for (int s = 0; s < CHUNKL; ++s) {
        int t = t0 + s;
        float xv0 = (i < 8) ? xb0[t * 8 + i] : 0.f;
        float xv1 = (i < 8) ? xb1[t * 8 + i] : 0.f;
        float innov0 = xv0 - b_i - dot16_regs(Brow, mu0);
        float innov1 = xv1 - b_i - dot16_regs(Brow, mu1);

        float iva[8], ivb[8];
        #pragma unroll
        for (int j = 0; j < 8; ++j) {
            iva[j] = __shfl_sync(FULL, innov0, j, 16);
            ivb[j] = __shfl_sync(FULL, innov1, j, 16);
        }

        const float* Nr = sN + (s * 8 + (i & 7)) * MP;
        float4 n0 = *(const float4*)(Nr), n1 = *(const float4*)(Nr + 4);
        float qf0 = n0.x * iva[0] + n0.y * iva[1] + n0.z * iva[2] + n0.w * iva[3]
                  + n1.x * iva[4] + n1.y * iva[5] + n1.z * iva[6] + n1.w * iva[7];
        float qf1 = n0.x * ivb[0] + n0.y * ivb[1] + n0.z * ivb[2] + n0.w * ivb[3]
                  + n1.x * ivb[4] + n1.y * ivb[5] + n1.z * ivb[6] + n1.w * ivb[7];
        sred0 += (i < 8) ? innov0 * qf0 : 0.f;
        sred1 += (i < 8) ? innov1 * qf1 : 0.f;

        const float* Cs = sC + s * 128;
        #pragma unroll
        for (int j = 0; j < 8; ++j) {
            float qa = __shfl_sync(FULL, qf0, j, 16);
            float qb = __shfl_sync(FULL, qf1, j, 16);
            float cji = Cs[j * 16 + i];
            lv0 = fmaf(cji, qa, lv0);
            lv1 = fmaf(cji, qb, lv1);
        }

        const float* Mr = sM + (s * 16 + i) * MP;
        float4 m0 = *(const float4*)(Mr), m1 = *(const float4*)(Mr + 4);
        float mi0 = m0.x * iva[0] + m0.y * iva[1] + m0.z * iva[2] + m0.w * iva[3]
                  + m1.x * iva[4] + m1.y * iva[5] + m1.z * iva[6] + m1.w * iva[7];
        float mi1 = m0.x * ivb[0] + m0.y * ivb[1] + m0.z * ivb[2] + m0.w * ivb[3]
                  + m1.x * ivb[4] + m1.y * ivb[5] + m1.z * ivb[6] + m1.w * ivb[7];
        float mn0 = a_i + dot16_regs(Arow, mu0) + mi0;
        float mn1 = a_i + dot16_regs(Arow, mu1) + mi1;
        own0 = mn0; own1 = mn1;
        #pragma unroll
        for (int k = 0; k < 16; ++k) {
            mu0[k] = __shfl_sync(FULL, mn0, k, 16);
            mu1[k] = __shfl_sync(FULL, mn1, k, 16);
        }
    }

    g_p[(chunk * NBATCH + b0)     * 16 + i] = own0;
    g_p[(chunk * NBATCH + b0 + 1) * 16 + i] = own1;
    g_l[(chunk * NBATCH + b0)     * 16 + i] = lv0;
    g_l[(chunk * NBATCH + b0 + 1) * 16 + i] = lv1;
    #pragma unroll
    for (int off = 1; off < 16; off <<= 1) {
        sred0 += __shfl_xor_sync(FULL, sred0, off, 16);
        sred1 += __shfl_xor_sync(FULL, sred1, off, 16);
    }
    if (i == 0) {
        g_cnst[chunk * NBATCH + b0]     = sred0;
        g_cnst[chunk * NBATCH + b0 + 1] = sred1;
    }
}

// =====================================================================
// Combine2 (two-level scan): grid 128 x 256 thr (8 warps, 2 batches).
// Phase 1: warp w -> zero-init response P_w of super w (8-chain).
// Phase 2: warp 0 -> scan over 8 supers via HH (smem).
// Phase 3: warp w -> rescan super w from its true start, emit mustart.
// Serial depth 24 vs 64; loads hidden by 8-warp occupancy.
// =====================================================================
__global__ void __launch_bounds__(256, 1)
combine2_kernel(const float* __restrict__ a0)
{
    __shared__ __align__(16) float sHH[NSUPER * 256];  // 8 KB
    __shared__ float sP[NSUPER][2][16];
    __shared__ float sS0[NSUPER][2][16];

    const unsigned FULL = 0xffffffffu;
    int tid = threadIdx.x;
    int lane = tid & 31, w = tid >> 5;
    int g = lane >> 4, i = lane & 15;
    int batch = blockIdx.x * 2 + g;

    // stage HH cooperatively (512 float4, 2 per thread)
    {
        const float4* src = (const float4*)g_HH;
        float4* dst = (float4*)sHH;
        dst[tid] = src[tid];
        dst[tid + 256] = src[tid + 256];
    }

    // ---- phase 1: P_w = zero-init response of super w ----
    float mu[16];
    #pragma unroll
    for (int k = 0; k < 16; ++k) mu[k] = 0.f;
    float own = 0.f;
    #pragma unroll
    for (int k2 = 0; k2 < 8; ++k2) {
        int c = w * 8 + k2;
        const float4* Hp = (const float4*)(g_H + c * 256 + i * 16);
        float4 h0 = Hp[0], h1 = Hp[1], h2 = Hp[2], h3 = Hp[3];
        float pv = g_p[(c * NBATCH + batch) * 16 + i];
        float mn = pv + dot16_tree(h0, h1, h2, h3, mu);
        own = mn;
        #pragma unroll
        for (int k = 0; k < 16; ++k) mu[k] = __shfl_sync(FULL, mn, k, 16);
    }
    sP[w][g][i] = own;
    __syncthreads();

    // ---- phase 2: warp 0 scans the 8 supers ----
    if (w == 0) {
        float own2 = a0[i];
        float mu2[16];
        #pragma unroll
        for (int k = 0; k < 16; ++k) mu2[k] = __shfl_sync(FULL, own2, k, 16);
        #pragma unroll
        for (int s = 0; s < NSUPER; ++s) {
            sS0[s][g][i] = own2;
            const float4* Qp = (const float4*)(sHH + s * 256 + i * 16);
            float4 q0 = Qp[0], q1 = Qp[1], q2 = Qp[2], q3 = Qp[3];
            float mn = sP[s][g][i] + dot16_tree(q0, q1, q2, q3, mu2);
            own2 = mn;
            #pragma unroll
            for (int k = 0; k < 16; ++k) mu2[k] = __shfl_sync(FULL, mn, k, 16);
        }
    }
    __syncthreads();

    // ---- phase 3: warp w rescans super w from its true start ----
    float own3 = sS0[w][g][i];
    float mu3[16];
    #pragma unroll
    for (int k = 0; k < 16; ++k) mu3[k] = __shfl_sync(FULL, own3, k, 16);
    #pragma unroll
    for (int k2 = 0; k2 < 8; ++k2) {
        int c = w * 8 + k2;
        g_mustart[(c * NBATCH + batch) * 16 + i] = own3;
        const float4* Hp = (const float4*)(g_H + c * 256 + i * 16);
        float4 h0 = Hp[0], h1 = Hp[1], h2 = Hp[2], h3 = Hp[3];
        float pv = g_p[(c * NBATCH + batch) * 16 + i];
        float mn = pv + dot16_tree(h0, h1, h2, h3, mu3);
        own3 = mn;
        #pragma unroll
        for (int k = 0; k < 16; ++k) mu3[k] = __shfl_sync(FULL, mn, k, 16);
    }
}

// =====================================================================
// eval: per-batch quadform evaluation + final sum.
// =====================================================================
__global__ void __launch_bounds__(32, 1)
eval_kernel(float* __restrict__ out)
{
    const unsigned FULL = 0xffffffffu;
    const float LOG2PI = 1.8378770664093453f;
    int lane = threadIdx.x;
    int g = lane >> 4, i = lane & 15;
    int batch = blockIdx.x * 2 + g;

    float acc = 0.f;

    #pragma unroll 2
    for (int c = 0; c < NCHUNK; ++c) {
        float mo = g_mustart[(c * NBATCH + batch) * 16 + i];
        float lv = g_l[(c * NBATCH + batch) * 16 + i];
        float mu[16];
        #pragma unroll
        for (int k = 0; k < 16; ++k) mu[k] = __shfl_sync(FULL, mo, k, 16);
        const float4* Qp = (const float4*)(g_Q + c * 256 + i * 16);
        float4 q0 = Qp[0], q1 = Qp[1], q2 = Qp[2], q3 = Qp[3];
        float qi = dot16_tree(q0, q1, q2, q3, mu);
        acc += mo * (qi - 2.f * lv);
        if (i == (c & 15))
            acc += g_cnst[c * NBATCH + batch] + g_ldc[c] + 128.f * LOG2PI;
    }

    #pragma unroll
    for (int off = 1; off < 16; off <<= 1)
        acc += __shfl_xor_sync(FULL, acc, off, 16);
    if (i == 0) out[batch] = 0.5f * acc;
}

// =====================================================================
// Launcher
// =====================================================================
extern "C" void kernel_launch(void* const* d_in, const int* in_sizes, int n_in,
                              void* d_out, int out_size)
{
    const float* x  = (const float*)d_in[0];
    const float* a  = (const float*)d_in[1];
    const float* b  = (const float*)d_in[2];
    const float* A  = (const float*)d_in[3];
    const float* B  = (const float*)d_in[4];
    const float* U  = (const float*)d_in[5];
    const float* V  = (const float*)d_in[6];
    const float* W  = (const float*)d_in[7];
    const float* a0 = (const float*)d_in[8];
    const float* A0 = (const float*)d_in[9];
    float* out = (float*)d_out;

    riccati_kernel<<<1, 256>>>(A, B, U, V, W, A0);
    prep_kernel<<<NCHUNK, 256>>>(A, B);
    hierH_kernel<<<NSUPER, 256>>>();
    passB_kernel<<<NCHUNK * (NBATCH / 32), 256>>>(x, a, b, A, B);
    combine2_kernel<<<NBATCH / 2, 256>>>(a0);
    eval_kernel<<<NBATCH / 2, 32>>>(out);
}